// round 4
// baseline (speedup 1.0000x reference)
#include <cuda_runtime.h>
#include <math.h>

// Problem constants: S=16 samples, B=128 batch, T=200 steps, L=64 latent,
// R=16 rank, H=256 hidden. One persistent CTA per batch element.
#define S_DIM 16
#define B_DIM 128
#define T_DIM 200
#define L_DIM 64
#define R_DIM 16
#define H_DIM 256
#define NT    256   // threads per CTA
#define LP    65    // padded row stride for 64x64 matrices (conflict-free columns)
#define HS    260   // padded row stride for hidden activations (float4-able)
#define KP    17    // padded row stride for K tile

struct __align__(16) SmemNLF {
  float w1[L_DIM * H_DIM];   // (L,H) row-major
  float w2[H_DIM * L_DIM];   // (H,L) row-major
  float b1[H_DIM];
  float b2[L_DIM];
  float zs[S_DIM * L_DIM];   // z_prev  [s][l]
  float hid[S_DIM * HS];     // tanh(layer1) [s][h]
  float ms[S_DIM * L_DIM];   // mean_fn output [s][l]
  float A [L_DIM * LP];      // workspace: P_p then J_f (full symmetric)
  float Lb[L_DIM * LP];      // cholesky factor (zeros above diag)
  float Li[L_DIM * LP];      // triangular inverse (zeros above diag)
  float Ksm[L_DIM * KP];     // K_t as (L,R)
  float wsm[S_DIM * L_DIM];  // w_t [s][l]
  float kt[L_DIM];
  float mp[L_DIM];
  float hf[L_DIM];
  float mf[L_DIM];
  float yv[L_DIM];
  float invd[L_DIM];
  float Qs[L_DIM];
  float m0s[L_DIM];
  float J0s[L_DIM];
  float sqP0[L_DIM];
};

__device__ __forceinline__ float softplus_f(float x) {
  // jax.nn.softplus = logaddexp(x, 0) = max(x,0) + log1p(exp(-|x|))
  return fmaxf(x, 0.0f) + log1pf(expf(-fabsf(x)));
}

// Right-looking Cholesky of A (64x64, lower triangle valid) into Lb
// (full matrix, exact zeros above the diagonal). One __syncthreads per
// column. A's trailing lower triangle is destroyed; column j of A stays
// raw during iteration j so the scale and the update never conflict.
__device__ __forceinline__ void chol64(float* __restrict__ A,
                                       float* __restrict__ Lb, int tid) {
  const int i = tid & 63;
  const int g = tid >> 6;          // 0..3 residue class for trailing update
  const int iwmax = i | 31;        // warp-uniform max row in this warp
  for (int j = 0; j < 64; ++j) {
    float d = A[j * LP + j];       // broadcast
    float sinv = rsqrtf(d);        // 1/sqrt(d)
    if (g == 0)
      Lb[i * LP + j] = (i >= j) ? A[i * LP + j] * sinv : 0.0f;
    if (j < iwmax) {
      float f = A[i * LP + j] * (sinv * sinv);   // A[i][j]/d
      int kk = j + 1;
      kk += (g - kk) & 3;          // align kk to this thread's residue class
      for (; kk < 64; kk += 4)
        if (kk <= i) A[i * LP + kk] -= f * A[kk * LP + j];
    }
    __syncthreads();
  }
}

// Li = Lb^{-1} (lower). Deferred-scaling column-parallel forward
// substitution: 4 threads per column (16 rows each), one barrier per step,
// single final scaling pass. Fills exact zeros above the diagonal so all
// downstream consumers can run full / warp-uniform-truncated loops.
__device__ __forceinline__ void triinv64(const float* __restrict__ Lb,
                                         float* __restrict__ Li,
                                         const float* __restrict__ invd,
                                         int tid) {
  for (int idx = tid; idx < 64 * 64; idx += NT) {
    int r = idx >> 6, c = idx & 63;
    Li[r * LP + c] = (r == c) ? 1.0f : 0.0f;
  }
  const int c  = tid & 63;
  const int p  = tid >> 6;
  const int r0 = p * 16, r1 = r0 + 16;
  const int cw = c & 32;           // warp-uniform min column in this warp
  __syncthreads();
  for (int j = 0; j < 63; ++j) {
    if (j >= cw) {                 // x_j == 0 for all columns of this warp otherwise
      float xj = Li[j * LP + c] * invd[j];
      int st = (j + 1 > r0) ? (j + 1) : r0;
      for (int r = st; r < r1; ++r)
        Li[r * LP + c] -= Lb[r * LP + j] * xj;
    }
    __syncthreads();
  }
  for (int idx = tid; idx < 64 * 64; idx += NT) {
    int r = idx >> 6, c2 = idx & 63;
    Li[r * LP + c2] *= invd[r];
  }
  __syncthreads();
}

// Load per-step inputs k_t, K_t, w_t into SMEM (all coalesced / float4).
__device__ __forceinline__ void load_step(SmemNLF* sm,
    const float* __restrict__ gk, const float* __restrict__ gK,
    const float* __restrict__ gw, int b, int t, int tid) {
  if (tid < L_DIM)
    sm->kt[tid] = gk[((size_t)b * T_DIM + t) * L_DIM + tid];
  {
    // K_t: 1024 contiguous floats -> Ksm (L, KP)
    const float4* src =
        (const float4*)(gK + ((size_t)b * T_DIM + t) * (L_DIM * R_DIM));
    float4 v = src[tid];
    int l = tid >> 2, r = (tid & 3) * 4;
    float* dst = &sm->Ksm[l * KP + r];
    dst[0] = v.x; dst[1] = v.y; dst[2] = v.z; dst[3] = v.w;
  }
  {
    // w_t: 16 rows of 64 contiguous floats
    int s = tid >> 4, l4 = (tid & 15) * 4;
    const float4* src = (const float4*)(
        gw + (((size_t)t * S_DIM + s) * B_DIM + b) * L_DIM + l4);
    *(float4*)&sm->wsm[s * L_DIM + l4] = *src;
  }
}

// z_f[s][i] = mf[i] + sum_j Li[j][i] * w[s][j]  (Li = Lf^{-1}; L^{-T} matvec)
// Also writes zs (next-step MLP input) and the z_f output slab.
__device__ __forceinline__ void zf_store(SmemNLF* sm, float* __restrict__ out_z,
                                         int b, int t, int tid) {
  const int i = tid & 63, p = tid >> 6;
  const float base = sm->mf[i];
  float a0 = base, a1 = base, a2 = base, a3 = base;
  const float* wr0 = &sm->wsm[(4 * p + 0) * L_DIM];
  const float* wr1 = &sm->wsm[(4 * p + 1) * L_DIM];
  const float* wr2 = &sm->wsm[(4 * p + 2) * L_DIM];
  const float* wr3 = &sm->wsm[(4 * p + 3) * L_DIM];
  const int j0 = i & 32;           // warp-uniform; Li[j][i]==0 for j<i
  for (int j = j0; j < 64; ++j) {
    float lv = sm->Li[j * LP + i];
    a0 += lv * wr0[j]; a1 += lv * wr1[j];
    a2 += lv * wr2[j]; a3 += lv * wr3[j];
  }
  float acc[4] = {a0, a1, a2, a3};
#pragma unroll
  for (int q = 0; q < 4; ++q) {
    int s = 4 * p + q;
    sm->zs[s * L_DIM + i] = acc[q];
    out_z[(((size_t)s * B_DIM + b) * T_DIM + t) * L_DIM + i] = acc[q];
  }
}

extern __shared__ float smem_raw_nlf[];

__global__ void __launch_bounds__(NT, 1)
NonlinearFilter_24721831756601_kernel(
    const float* __restrict__ gk,     // (B,T,L)
    const float* __restrict__ gK,     // (B,T,L,R)
    const float* __restrict__ glogQ,  // (L)
    const float* __restrict__ gm0,    // (L)
    const float* __restrict__ glogv0, // (L)
    const float* __restrict__ gW1,    // (L,H)
    const float* __restrict__ gb1,    // (H)
    const float* __restrict__ gW2,    // (H,L)
    const float* __restrict__ gb2,    // (L)
    const float* __restrict__ gw,     // (T,S,B,L)
    float* __restrict__ out) {
  SmemNLF* sm = (SmemNLF*)smem_raw_nlf;
  const int tid = threadIdx.x;
  const int b = blockIdx.x;

  const size_t ZN = (size_t)S_DIM * B_DIM * T_DIM * L_DIM;
  const size_t MN = (size_t)B_DIM * T_DIM * L_DIM;
  const size_t PN = (size_t)B_DIM * T_DIM * L_DIM * L_DIM;
  float* out_z  = out;             // z_f     (S,B,T,L)
  float* out_mf = out + ZN;        // m_f     (B,T,L)
  float* out_mp = out_mf + MN;     // m_p     (B,T,L)
  float* out_Pf = out_mp + MN;     // P_f_chol(B,T,L,L)
  float* out_Pp = out_Pf + PN;     // P_p_chol(B,T,L,L)

  // ---- one-time loads ----
  for (int idx = tid; idx < L_DIM * H_DIM; idx += NT) sm->w1[idx] = gW1[idx];
  for (int idx = tid; idx < H_DIM * L_DIM; idx += NT) sm->w2[idx] = gW2[idx];
  if (tid < H_DIM) sm->b1[tid] = gb1[tid];
  if (tid < L_DIM) {
    sm->b2[tid]  = gb2[tid];
    sm->Qs[tid]  = softplus_f(glogQ[tid]);
    float p0     = softplus_f(glogv0[tid]);
    sm->J0s[tid] = 1.0f / p0;
    sm->sqP0[tid] = sqrtf(p0);
    sm->m0s[tid] = gm0[tid];
  }
  load_step(sm, gk, gK, gw, b, 0, tid);
  __syncthreads();

  // ================= t = 0 =================
  // Jf0 = diag(J0) + K0 K0^T   (full symmetric fill)
  for (int idx = tid; idx < 64 * 64; idx += NT) {
    int i = idx >> 6, j = idx & 63;
    float acc = (i == j) ? sm->J0s[i] : 0.0f;
#pragma unroll
    for (int r = 0; r < R_DIM; ++r)
      acc += sm->Ksm[i * KP + r] * sm->Ksm[j * KP + r];
    sm->A[i * LP + j] = acc;
  }
  if (tid < L_DIM)  // h_f0 = J0*m0 + k0  (same-thread values only)
    sm->hf[tid] = sm->J0s[tid] * sm->m0s[tid] + sm->kt[tid];
  __syncthreads();

  chol64(sm->A, sm->Lb, tid);
  if (tid < L_DIM) sm->invd[tid] = __fdividef(1.0f, sm->Lb[tid * LP + tid]);
  triinv64(sm->Lb, sm->Li, sm->invd, tid);   // Li = Lf0^{-1}

  // yv = Li * hf ; meanwhile write P_p_chol0 (diag sqrt(P0)) and m_p0
  if (tid < L_DIM) {
    float acc = 0.0f;
    int jend = (tid | 31) + 1;
    for (int j = 0; j < jend; ++j) acc += sm->Li[tid * LP + j] * sm->hf[j];
    sm->yv[tid] = acc;
    out_mp[((size_t)b * T_DIM + 0) * L_DIM + tid] = sm->m0s[tid];
  }
  {
    float* dst = out_Pp + ((size_t)b * T_DIM + 0) * (L_DIM * L_DIM);
    for (int idx = tid; idx < 64 * 64; idx += NT) {
      int i = idx >> 6, j = idx & 63;
      dst[idx] = (i == j) ? sm->sqP0[i] : 0.0f;
    }
  }
  __syncthreads();
  // mf = Li^T * yv ; write m_f0 and P_f_chol0 = Li^T
  if (tid < L_DIM) {
    float acc = 0.0f;
    for (int j = tid & 32; j < 64; ++j) acc += sm->Li[j * LP + tid] * sm->yv[j];
    sm->mf[tid] = acc;
    out_mf[((size_t)b * T_DIM + 0) * L_DIM + tid] = acc;
  }
  {
    float* dst = out_Pf + ((size_t)b * T_DIM + 0) * (L_DIM * L_DIM);
    for (int idx = tid; idx < 64 * 64; idx += NT) {
      int i = idx >> 6, j = idx & 63;
      dst[idx] = sm->Li[j * LP + i];
    }
  }
  __syncthreads();
  zf_store(sm, out_z, b, 0, tid);
  __syncthreads();

  // ================= t = 1 .. T-1 =================
  for (int t = 1; t < T_DIM; ++t) {
    load_step(sm, gk, gK, gw, b, t, tid);

    // ---- MLP layer 1: hid[s][h] = tanh(b1[h] + sum_l zs[s][l] W1[l][h]) ----
    {
      float acc[S_DIM];
      float bb = sm->b1[tid];
#pragma unroll
      for (int s = 0; s < S_DIM; ++s) acc[s] = bb;
      for (int l = 0; l < L_DIM; l += 4) {
        float wa = sm->w1[(l + 0) * H_DIM + tid];
        float wb = sm->w1[(l + 1) * H_DIM + tid];
        float wc = sm->w1[(l + 2) * H_DIM + tid];
        float wd = sm->w1[(l + 3) * H_DIM + tid];
#pragma unroll
        for (int s = 0; s < S_DIM; ++s) {
          float4 z4 = *(const float4*)&sm->zs[s * L_DIM + l];
          acc[s] += z4.x * wa + z4.y * wb + z4.z * wc + z4.w * wd;
        }
      }
#pragma unroll
      for (int s = 0; s < S_DIM; ++s) sm->hid[s * HS + tid] = tanhf(acc[s]);
    }
    __syncthreads();

    // ---- MLP layer 2: ms[s][j] = b2[j] + sum_h hid[s][h] W2[h][j] ----
    {
      const int j = tid & 63, p = tid >> 6;
      float acc[4];
      float bb = sm->b2[j];
#pragma unroll
      for (int q = 0; q < 4; ++q) acc[q] = bb;
      for (int h = 0; h < H_DIM; h += 4) {
        float wa = sm->w2[(h + 0) * L_DIM + j];
        float wb = sm->w2[(h + 1) * L_DIM + j];
        float wc = sm->w2[(h + 2) * L_DIM + j];
        float wd = sm->w2[(h + 3) * L_DIM + j];
#pragma unroll
        for (int q = 0; q < 4; ++q) {
          float4 h4 = *(const float4*)&sm->hid[(4 * p + q) * HS + h];
          acc[q] += h4.x * wa + h4.y * wb + h4.z * wc + h4.w * wd;
        }
      }
#pragma unroll
      for (int q = 0; q < 4; ++q) sm->ms[(4 * p + q) * L_DIM + j] = acc[q];
    }
    __syncthreads();

    // ---- m_p = mean_s ms ----
    if (tid < L_DIM) {
      float acc = 0.0f;
#pragma unroll
      for (int s = 0; s < S_DIM; ++s) acc += sm->ms[s * L_DIM + tid];
      sm->mp[tid] = acc * (1.0f / (float)S_DIM);
    }
    __syncthreads();

    // ---- P_p = diag(Q) + Ezz - mp mp^T ----
    for (int idx = tid; idx < 64 * 64; idx += NT) {
      int i = idx >> 6, j = idx & 63;
      float acc = 0.0f;
#pragma unroll
      for (int s = 0; s < S_DIM; ++s)
        acc += sm->ms[s * L_DIM + i] * sm->ms[s * L_DIM + j];
      acc = acc * (1.0f / (float)S_DIM) - sm->mp[i] * sm->mp[j];
      if (i == j) acc += sm->Qs[i];
      sm->A[i * LP + j] = acc;
    }
    __syncthreads();

    chol64(sm->A, sm->Lb, tid);                       // Lb = Lp
    if (tid < L_DIM) sm->invd[tid] = __fdividef(1.0f, sm->Lb[tid * LP + tid]);
    triinv64(sm->Lb, sm->Li, sm->invd, tid);          // Li = Lp^{-1}

    // yv = Li * mp ; write P_p_chol (=Lp) and m_p outputs
    if (tid < L_DIM) {
      float acc = 0.0f;
      int jend = (tid | 31) + 1;
      for (int j = 0; j < jend; ++j) acc += sm->Li[tid * LP + j] * sm->mp[j];
      sm->yv[tid] = acc;
      out_mp[((size_t)b * T_DIM + t) * L_DIM + tid] = sm->mp[tid];
    }
    {
      float* dst = out_Pp + ((size_t)b * T_DIM + t) * (L_DIM * L_DIM);
      for (int idx = tid; idx < 64 * 64; idx += NT) {
        int i = idx >> 6, j = idx & 63;
        dst[idx] = sm->Lb[i * LP + j];
      }
    }
    __syncthreads();

    // hf = Li^T yv + k_t ; meanwhile J_f = Li^T Li + K K^T into A
    if (tid < L_DIM) {
      float acc = sm->kt[tid];
      for (int j = tid & 32; j < 64; ++j) acc += sm->Li[j * LP + tid] * sm->yv[j];
      sm->hf[tid] = acc;
    }
    for (int idx = tid; idx < 64 * 64; idx += NT) {
      int i = idx >> 6, j = idx & 63;
      float acc = 0.0f;
      int k0 = (i > (j & 32)) ? i : (j & 32);  // warp-uniform; zeros skipped
      for (int k2 = k0; k2 < 64; ++k2)
        acc += sm->Li[k2 * LP + i] * sm->Li[k2 * LP + j];
#pragma unroll
      for (int r = 0; r < R_DIM; ++r)
        acc += sm->Ksm[i * KP + r] * sm->Ksm[j * KP + r];
      sm->A[i * LP + j] = acc;
    }
    __syncthreads();

    chol64(sm->A, sm->Lb, tid);                       // Lb = Lf
    if (tid < L_DIM) sm->invd[tid] = __fdividef(1.0f, sm->Lb[tid * LP + tid]);
    triinv64(sm->Lb, sm->Li, sm->invd, tid);          // Li = Lf^{-1}

    // yv = Li * hf ; write P_f_chol = Li^T
    if (tid < L_DIM) {
      float acc = 0.0f;
      int jend = (tid | 31) + 1;
      for (int j = 0; j < jend; ++j) acc += sm->Li[tid * LP + j] * sm->hf[j];
      sm->yv[tid] = acc;
    }
    {
      float* dst = out_Pf + ((size_t)b * T_DIM + t) * (L_DIM * L_DIM);
      for (int idx = tid; idx < 64 * 64; idx += NT) {
        int i = idx >> 6, j = idx & 63;
        dst[idx] = sm->Li[j * LP + i];
      }
    }
    __syncthreads();

    // mf = Li^T yv ; write m_f
    if (tid < L_DIM) {
      float acc = 0.0f;
      for (int j = tid & 32; j < 64; ++j) acc += sm->Li[j * LP + tid] * sm->yv[j];
      sm->mf[tid] = acc;
      out_mf[((size_t)b * T_DIM + t) * L_DIM + tid] = acc;
    }
    __syncthreads();

    zf_store(sm, out_z, b, t, tid);
    __syncthreads();
  }
}

extern "C" void kernel_launch(void* const* d_in, const int* in_sizes, int n_in,
                              void* d_out, int out_size) {
  (void)in_sizes; (void)n_in; (void)out_size;
  static int attr_set = 0;
  if (!attr_set) {
    cudaFuncSetAttribute(NonlinearFilter_24721831756601_kernel,
                         cudaFuncAttributeMaxDynamicSharedMemorySize,
                         (int)sizeof(SmemNLF));
    attr_set = 1;
  }
  NonlinearFilter_24721831756601_kernel
      <<<B_DIM, NT, sizeof(SmemNLF)>>>(
          (const float*)d_in[0],  // k      (B,T,L)
          (const float*)d_in[1],  // K      (B,T,L,R)
          (const float*)d_in[2],  // log_Q  (L)
          (const float*)d_in[3],  // m0     (L)
          (const float*)d_in[4],  // log_v0 (L)
          (const float*)d_in[5],  // W1     (L,H)
          (const float*)d_in[6],  // b1     (H)
          (const float*)d_in[7],  // W2     (H,L)
          (const float*)d_in[8],  // b2     (L)
          (const float*)d_in[9],  // w      (T,S,B,L)
          (float*)d_out);
}